// round 17
// baseline (speedup 1.0000x reference)
#include <cuda_runtime.h>

// ce_loss_aux: masked one-hot binary CE.
// 2048 blocks x 256 threads, contiguous 1024-pair chunks (PPT=4): finer
// work quantum for better SM balance. Batched float4 loads, 8-position
// log-products (one __logf per 4 pairs), FMA one-hot selects (labels are
// exactly 0/1), deterministic fixed-point int64 atomic tail.

#define NTHREADS 256
#define PPT 4                                   // float4-pairs per thread
#define CHUNK_PAIRS (NTHREADS * PPT)            // 1024 pairs / block
#define FP_SCALE 1048576.0f                     // 2^20

__device__ unsigned long long g_loss;           // fixed-point loss sum
__device__ int                g_len;            // doc_len sum
__device__ unsigned int       g_counter;        // zero-init; reset by last block

__global__ __launch_bounds__(NTHREADS)
void ce_fused_kernel(const float* __restrict__ y_true,
                     const float* __restrict__ y_pred,
                     const int*   __restrict__ doc_len,
                     float* __restrict__ out,
                     int B, int L, int chunksPerRow, int nBlocks)
{
    const int tid   = threadIdx.x;
    const int b     = blockIdx.x / chunksPerRow;
    const int chunk = blockIdx.x - b * chunksPerRow;
    const int d     = __ldg(&doc_len[b]);

    const int pairBase = chunk * CHUNK_PAIRS;
    const int lStart   = pairBase * 2;

    float acc = 0.0f;

    if (lStart < d) {
        const float4* t4 = reinterpret_cast<const float4*>(y_true) + (size_t)b * (L >> 1);
        const float4* p4 = reinterpret_cast<const float4*>(y_pred) + (size_t)b * (L >> 1);

        if (lStart + CHUNK_PAIRS * 2 <= d) {
            // ---- fully valid: batched loads, 8-way product, 1 log / 4 pairs ----
            float4 t[PPT], p[PPT];
            #pragma unroll
            for (int i = 0; i < PPT; i++)
                t[i] = __ldg(&t4[pairBase + i * NTHREADS + tid]);
            #pragma unroll
            for (int i = 0; i < PPT; i++)
                p[i] = __ldg(&p4[pairBase + i * NTHREADS + tid]);

            float m = 1.0f;
            #pragma unroll
            for (int i = 0; i < PPT; i++) {
                float s0 = t[i].x * p[i].x + t[i].y * p[i].y;  // exact one-hot select
                float s1 = t[i].z * p[i].z + t[i].w * p[i].w;
                m *= s0 * s1;                    // 8 factors >= 1e-4 -> m >= 1e-32
            }
            acc -= __logf(m);
        } else {
            // ---- boundary chunk: per-pair predication on d ----
            #pragma unroll
            for (int i = 0; i < PPT; i++) {
                int pr = pairBase + i * NTHREADS + tid;
                int l0 = pr << 1;
                if (l0 < d) {
                    float4 t = __ldg(&t4[pr]);
                    float4 p = __ldg(&p4[pr]);
                    float s0 = t.x * p.x + t.y * p.y;
                    float s1 = (l0 + 1 < d) ? (t.z * p.z + t.w * p.w) : 1.0f;
                    acc -= __logf(s0 * s1);
                }
            }
        }
    }

    // ---- block reduction ----
    __shared__ float red[NTHREADS / 32];
    #pragma unroll
    for (int o = 16; o > 0; o >>= 1)
        acc += __shfl_down_sync(0xFFFFFFFFu, acc, o);
    if ((tid & 31) == 0) red[tid >> 5] = acc;
    __syncthreads();

    // ---- atomic accumulation (exact integer adds -> deterministic) ----
    __shared__ bool amLast;
    if (tid == 0) {
        float v = 0.0f;
        #pragma unroll
        for (int i = 0; i < NTHREADS / 32; i++) v += red[i];
        unsigned long long q = (unsigned long long)__float2ll_rn(v * FP_SCALE);
        atomicAdd(&g_loss, q);
        if (chunk == 0) atomicAdd(&g_len, d);
        __threadfence();
        unsigned int prev = atomicAdd(&g_counter, 1u);
        amLast = (prev == (unsigned int)(nBlocks - 1));
    }
    __syncthreads();

    // ---- last block: finish from two scalars, reset for graph replay ----
    if (amLast && tid == 0) {
        unsigned long long ls = g_loss;
        int                ln = g_len;
        out[0] = (float)((double)ls / (double)FP_SCALE / (double)ln);
        g_loss    = 0ull;
        g_len     = 0;
        g_counter = 0;
    }
}

extern "C" void kernel_launch(void* const* d_in, const int* in_sizes, int n_in,
                              void* d_out, int out_size)
{
    const float* y_true  = (const float*)d_in[0];
    const float* y_pred  = (const float*)d_in[1];
    const int*   doc_len = (const int*)d_in[2];
    float*       out     = (float*)d_out;

    int B = in_sizes[2];
    int L = in_sizes[0] / (2 * B);

    int pairsPerRow  = L >> 1;
    int chunksPerRow = (pairsPerRow + CHUNK_PAIRS - 1) / CHUNK_PAIRS;
    int nBlocks      = B * chunksPerRow;

    ce_fused_kernel<<<nBlocks, NTHREADS>>>(y_true, y_pred, doc_len, out,
                                           B, L, chunksPerRow, nBlocks);
}